// round 2
// baseline (speedup 1.0000x reference)
#include <cuda_runtime.h>
#include <math.h>

#define NN 100000
#define DEGQ 8
#define EE (NN*DEGQ)
#define LEAKY 0.2f

// ---------------- scratch (device globals; no allocation allowed) ----------
__device__ float g_nt [(size_t)NN * 128];
__device__ float g_ctx[(size_t)NN * 128];
__device__ float g_h1 [(size_t)NN * 128];
__device__ float g_gi [(size_t)NN * 384];
__device__ float g_gh [(size_t)NN * 384];

__device__ __forceinline__ float lrelu_f(float x) { return x > 0.f ? x : LEAKY * x; }

// ---------------------------------------------------------------------------
// Generic tiled GEMM: C[M x Nout] = act(A[M x K] @ W[Nout x K]^T + bias)
// BM=64, BN=64, 256 threads, 4x4 microtile, full-K resident in smem.
// ACT: 0 = none, 1 = leaky_relu
// ---------------------------------------------------------------------------
template <int K, int ACT>
__global__ __launch_bounds__(256)
void gemm_kernel(const float* __restrict__ A, const float* __restrict__ W,
                 const float* __restrict__ bias, float* __restrict__ C,
                 int M, int Nout) {
    extern __shared__ float sm[];
    const int LDS_ = 68;               // 64 + pad
    float* At = sm;                    // [K][68]  (k-major, transposed)
    float* Wt = sm + K * LDS_;         // [K][68]

    const int tid = threadIdx.x;
    const int m0 = blockIdx.y * 64;
    const int n0 = blockIdx.x * 64;

    // load A tile (transposed into smem)
    for (int idx = tid; idx < 64 * (K / 4); idx += 256) {
        int row = idx / (K / 4);
        int kc = (idx % (K / 4)) * 4;
        float4 v = make_float4(0.f, 0.f, 0.f, 0.f);
        if (m0 + row < M) v = *(const float4*)(A + (size_t)(m0 + row) * K + kc);
        At[(kc + 0) * LDS_ + row] = v.x;
        At[(kc + 1) * LDS_ + row] = v.y;
        At[(kc + 2) * LDS_ + row] = v.z;
        At[(kc + 3) * LDS_ + row] = v.w;
    }
    // load W tile (Nout always a multiple of 64 here)
    for (int idx = tid; idx < 64 * (K / 4); idx += 256) {
        int row = idx / (K / 4);
        int kc = (idx % (K / 4)) * 4;
        float4 v = *(const float4*)(W + (size_t)(n0 + row) * K + kc);
        Wt[(kc + 0) * LDS_ + row] = v.x;
        Wt[(kc + 1) * LDS_ + row] = v.y;
        Wt[(kc + 2) * LDS_ + row] = v.z;
        Wt[(kc + 3) * LDS_ + row] = v.w;
    }
    __syncthreads();

    const int ty = tid >> 4, tx = tid & 15;
    float acc[4][4];
#pragma unroll
    for (int i = 0; i < 4; i++)
#pragma unroll
        for (int j = 0; j < 4; j++) acc[i][j] = 0.f;

#pragma unroll 16
    for (int k = 0; k < K; k++) {
        float4 a = *(float4*)(At + k * LDS_ + ty * 4);
        float4 b = *(float4*)(Wt + k * LDS_ + tx * 4);
        float av[4] = {a.x, a.y, a.z, a.w};
        float bv[4] = {b.x, b.y, b.z, b.w};
#pragma unroll
        for (int i = 0; i < 4; i++)
#pragma unroll
            for (int j = 0; j < 4; j++) acc[i][j] += av[i] * bv[j];
    }

    float4 bb = *(const float4*)(bias + n0 + tx * 4);
    float bv[4] = {bb.x, bb.y, bb.z, bb.w};
#pragma unroll
    for (int i = 0; i < 4; i++) {
        int row = m0 + ty * 4 + i;
        if (row < M) {
            float4 o;
            float v0 = acc[i][0] + bv[0];
            float v1 = acc[i][1] + bv[1];
            float v2 = acc[i][2] + bv[2];
            float v3 = acc[i][3] + bv[3];
            if (ACT == 1) { v0 = lrelu_f(v0); v1 = lrelu_f(v1); v2 = lrelu_f(v2); v3 = lrelu_f(v3); }
            o.x = v0; o.y = v1; o.z = v2; o.w = v3;
            *(float4*)(C + (size_t)row * Nout + n0 + tx * 4) = o;
        }
    }
}

// ---------------------------------------------------------------------------
// Edge kernel: per block -> 8 dst nodes (= 64 contiguous edges since
// dst = repeat(arange(N), 8)).
//   nn_e   = lrelu(W2 @ cat(atom[src], bond_e) + b2)       (never materialized)
//   logit  = lrelu(dot(h1[dst], Ww[0:128]) + dot(nn_e, Ww[128:256]) + bw)
//   score  = softmax over the 8 edges of each node
//   ctx    = elu( sum_e score_e * nt[src_e] )
// GEMM part: [64 edges x 192] @ W2^T[192 x 128], 256 threads, 4x8 microtile.
// ---------------------------------------------------------------------------
__global__ __launch_bounds__(256)
void edge_kernel(const float* __restrict__ atom, const float* __restrict__ bond,
                 const int* __restrict__ src, const float* __restrict__ h1,
                 const float* __restrict__ W2, const float* __restrict__ b2,
                 const float* __restrict__ Ww, const float* __restrict__ bw,
                 const float* __restrict__ nt, float* __restrict__ ctx) {
    extern __shared__ float sm[];
    const int LDW = 132;   // 128 + pad
    const int LDX = 68;    // 64 + pad
    float* Wt    = sm;                     // [192][132]
    float* Xt    = Wt + 192 * LDW;         // [192][68]
    float* slog  = Xt + 192 * LDX;         // [64]
    float* sscr  = slog + 64;              // [64]
    float* sndot = sscr + 64;              // [8]
    int*   ssrc  = (int*)(sndot + 8);      // [64]

    const int tid = threadIdx.x;
    const int nb = blockIdx.x * 8;            // first node of this block
    const long eb = (long)blockIdx.x * 64;    // first edge

    if (tid < 64) ssrc[tid] = src[eb + tid];
    __syncthreads();

    // stage W2 [128][192] transposed -> Wt[k][j]
    for (int idx = tid; idx < 128 * 48; idx += 256) {
        int j = idx / 48;
        int kc = (idx % 48) * 4;
        float4 v = *(const float4*)(W2 + (size_t)j * 192 + kc);
        Wt[(kc + 0) * LDW + j] = v.x;
        Wt[(kc + 1) * LDW + j] = v.y;
        Wt[(kc + 2) * LDW + j] = v.z;
        Wt[(kc + 3) * LDW + j] = v.w;
    }
    // stage edge inputs (gathered atom rows + bond rows), transposed -> Xt[k][e]
    for (int idx = tid; idx < 64 * 48; idx += 256) {
        int e = idx / 48;
        int kc = (idx % 48) * 4;
        float4 v;
        if (kc < 128) v = *(const float4*)(atom + (size_t)ssrc[e] * 128 + kc);
        else          v = *(const float4*)(bond + (size_t)(eb + e) * 64 + (kc - 128));
        Xt[(kc + 0) * LDX + e] = v.x;
        Xt[(kc + 1) * LDX + e] = v.y;
        Xt[(kc + 2) * LDX + e] = v.z;
        Xt[(kc + 3) * LDX + e] = v.w;
    }
    // per-node h1 . Ww[0:128] (+bw) : 32 threads per node
    {
        int g = tid >> 5, lane = tid & 31;
        const float* hr = h1 + (size_t)(nb + g) * 128;
        float s = hr[lane] * Ww[lane] + hr[lane + 32] * Ww[lane + 32] +
                  hr[lane + 64] * Ww[lane + 64] + hr[lane + 96] * Ww[lane + 96];
#pragma unroll
        for (int o = 16; o > 0; o >>= 1) s += __shfl_xor_sync(0xffffffffu, s, o);
        if (lane == 0) sndot[g] = s + bw[0];
    }
    __syncthreads();

    // GEMM: 64 x 128 x 192
    const int ty = tid >> 4, tx = tid & 15;
    float acc[4][8];
#pragma unroll
    for (int i = 0; i < 4; i++)
#pragma unroll
        for (int j = 0; j < 8; j++) acc[i][j] = 0.f;

#pragma unroll 8
    for (int k = 0; k < 192; k++) {
        float4 a  = *(float4*)(Xt + k * LDX + ty * 4);
        float4 b0 = *(float4*)(Wt + k * LDW + tx * 8);
        float4 b1 = *(float4*)(Wt + k * LDW + tx * 8 + 4);
        float av[4] = {a.x, a.y, a.z, a.w};
        float bv[8] = {b0.x, b0.y, b0.z, b0.w, b1.x, b1.y, b1.z, b1.w};
#pragma unroll
        for (int i = 0; i < 4; i++)
#pragma unroll
            for (int j = 0; j < 8; j++) acc[i][j] += av[i] * bv[j];
    }

    // epilogue: fold nn_e into logit contribution, reduce across tx
    float4 b2a = *(const float4*)(b2 + tx * 8);
    float4 b2b = *(const float4*)(b2 + tx * 8 + 4);
    float4 wwa = *(const float4*)(Ww + 128 + tx * 8);
    float4 wwb = *(const float4*)(Ww + 128 + tx * 8 + 4);
    float bbv[8] = {b2a.x, b2a.y, b2a.z, b2a.w, b2b.x, b2b.y, b2b.z, b2b.w};
    float wwv[8] = {wwa.x, wwa.y, wwa.z, wwa.w, wwb.x, wwb.y, wwb.z, wwb.w};
#pragma unroll
    for (int i = 0; i < 4; i++) {
        float s = 0.f;
#pragma unroll
        for (int j = 0; j < 8; j++) s += lrelu_f(acc[i][j] + bbv[j]) * wwv[j];
        // reduce across the 16 tx lanes (lane bit 4 carries ty parity -> untouched)
        s += __shfl_xor_sync(0xffffffffu, s, 1);
        s += __shfl_xor_sync(0xffffffffu, s, 2);
        s += __shfl_xor_sync(0xffffffffu, s, 4);
        s += __shfl_xor_sync(0xffffffffu, s, 8);
        if (tx == 0) slog[ty * 4 + i] = s;
    }
    __syncthreads();

    // per-node softmax over the 8 edges
    if (tid < 8) {
        float base = sndot[tid];
        float l[8];
        float m = -1e30f;
#pragma unroll
        for (int e = 0; e < 8; e++) {
            float v = lrelu_f(slog[tid * 8 + e] + base);
            l[e] = v;
            m = fmaxf(m, v);
        }
        float ssum = 0.f;
#pragma unroll
        for (int e = 0; e < 8; e++) { l[e] = expf(l[e] - m); ssum += l[e]; }
        float inv = 1.f / ssum;
#pragma unroll
        for (int e = 0; e < 8; e++) sscr[tid * 8 + e] = l[e] * inv;
    }
    __syncthreads();

    // weighted gather of nt[src], elu, store context: 32 threads per node
    {
        int g = tid >> 5, lane = tid & 31;
        float c0 = 0.f, c1 = 0.f, c2 = 0.f, c3 = 0.f;
#pragma unroll
        for (int e = 0; e < 8; e++) {
            const float* r = nt + (size_t)ssrc[g * 8 + e] * 128;
            float sc = sscr[g * 8 + e];
            c0 += sc * r[lane];
            c1 += sc * r[lane + 32];
            c2 += sc * r[lane + 64];
            c3 += sc * r[lane + 96];
        }
        c0 = c0 > 0.f ? c0 : (expf(c0) - 1.f);
        c1 = c1 > 0.f ? c1 : (expf(c1) - 1.f);
        c2 = c2 > 0.f ? c2 : (expf(c2) - 1.f);
        c3 = c3 > 0.f ? c3 : (expf(c3) - 1.f);
        float* o = ctx + (size_t)(nb + g) * 128;
        o[lane] = c0;
        o[lane + 32] = c1;
        o[lane + 64] = c2;
        o[lane + 96] = c3;
    }
}

// ---------------------------------------------------------------------------
// GRU elementwise combine
// ---------------------------------------------------------------------------
__global__ __launch_bounds__(256)
void gru_combine(const float* __restrict__ gi, const float* __restrict__ gh,
                 const float* __restrict__ h1, float* __restrict__ out) {
    int i = blockIdx.x * blockDim.x + threadIdx.x;
    if (i >= NN * 128) return;
    int n = i >> 7, c = i & 127;
    const float* gin = gi + (size_t)n * 384;
    const float* ghn = gh + (size_t)n * 384;
    float ir = gin[c], iz = gin[c + 128], inn = gin[c + 256];
    float hr = ghn[c], hz = ghn[c + 128], hn = ghn[c + 256];
    float r = 1.f / (1.f + expf(-(ir + hr)));
    float z = 1.f / (1.f + expf(-(iz + hz)));
    float nv = tanhf(inn + r * hn);
    out[i] = (1.f - z) * nv + z * h1[i];
}

// ---------------------------------------------------------------------------
extern "C" void kernel_launch(void* const* d_in, const int* in_sizes, int n_in,
                              void* d_out, int out_size) {
    const float* atom = (const float*)d_in[0];
    const float* bond = (const float*)d_in[1];
    const int*   src  = (const int*)d_in[2];
    // d_in[3] = dst (structurally e/8; unused)
    const float* W1   = (const float*)d_in[4];
    const float* b1   = (const float*)d_in[5];
    const float* W2   = (const float*)d_in[6];
    const float* b2   = (const float*)d_in[7];
    const float* Wa   = (const float*)d_in[8];
    const float* ba   = (const float*)d_in[9];
    const float* Ww   = (const float*)d_in[10];
    const float* bw   = (const float*)d_in[11];
    const float* W_ih = (const float*)d_in[12];
    const float* b_ih = (const float*)d_in[13];
    const float* W_hh = (const float*)d_in[14];
    const float* b_hh = (const float*)d_in[15];

    float* out = (float*)d_out;

    float *nt, *ctx, *gi, *gh, *h1fb;
    cudaGetSymbolAddress((void**)&nt,   g_nt);
    cudaGetSymbolAddress((void**)&ctx,  g_ctx);
    cudaGetSymbolAddress((void**)&gi,   g_gi);
    cudaGetSymbolAddress((void**)&gh,   g_gh);
    cudaGetSymbolAddress((void**)&h1fb, g_h1);

    // h1 is part of the output (final, h1) when out_size covers both
    float* h1 = (out_size >= 2 * NN * 128) ? (out + (size_t)NN * 128) : h1fb;

    const int GSM = 2 * 128 * 68 * sizeof(float);                 // 69632 B
    const int ESM = (192 * 132 + 192 * 68 + 64 + 64 + 8) * 4 + 64 * 4;  // ~154.4 KB

    cudaFuncSetAttribute(gemm_kernel<128, 1>, cudaFuncAttributeMaxDynamicSharedMemorySize, GSM);
    cudaFuncSetAttribute(gemm_kernel<128, 0>, cudaFuncAttributeMaxDynamicSharedMemorySize, GSM);
    cudaFuncSetAttribute(edge_kernel, cudaFuncAttributeMaxDynamicSharedMemorySize, ESM);

    const int MB = (NN + 63) / 64;  // 1563

    // 1) h1 = lrelu(atom @ W1^T + b1)  -> into output region
    gemm_kernel<128, 1><<<dim3(2, MB), 256, GSM>>>(atom, W1, b1, h1, NN, 128);
    // 2) nt = h1 @ Wa^T + ba
    gemm_kernel<128, 0><<<dim3(2, MB), 256, GSM>>>(h1, Wa, ba, nt, NN, 128);
    // 3) fused edge kernel -> context
    edge_kernel<<<NN / 8, 256, ESM>>>(atom, bond, src, h1, W2, b2, Ww, bw, nt, ctx);
    // 4) GRU input/hidden GEMMs
    gemm_kernel<128, 0><<<dim3(6, MB), 256, GSM>>>(ctx, W_ih, b_ih, gi, NN, 384);
    gemm_kernel<128, 0><<<dim3(6, MB), 256, GSM>>>(h1, W_hh, b_hh, gh, NN, 384);
    // 5) combine -> final
    gru_combine<<<(NN * 128 + 255) / 256, 256>>>(gi, gh, h1, out);
}

// round 3
// speedup vs baseline: 1.4105x; 1.4105x over previous
#include <cuda_runtime.h>
#include <math.h>

#define NN 100000
#define LEAKY 0.2f

constexpr int LDSZ = 132;   // 128 + 4 pad

// ---------------- scratch (device globals; no allocation allowed) ----------
__device__ float g_nt [(size_t)NN * 128];
__device__ float g_ctx[(size_t)NN * 128];
__device__ float g_h1 [(size_t)NN * 128];
__device__ float g_gi [(size_t)NN * 384];
__device__ float g_gh [(size_t)NN * 384];

__device__ __forceinline__ float lrelu_f(float x) { return x > 0.f ? x : LEAKY * x; }

__device__ __forceinline__ unsigned long long pack2(float lo, float hi) {
    unsigned long long r;
    asm("mov.b64 %0, {%1, %2};" : "=l"(r) : "f"(lo), "f"(hi));
    return r;
}
__device__ __forceinline__ void ffma2(unsigned long long& d, unsigned long long a, unsigned long long b) {
    asm("fma.rn.f32x2 %0, %1, %2, %0;" : "+l"(d) : "l"(a), "l"(b));
}
__device__ __forceinline__ float2 unpk(unsigned long long v) {
    float2 r;
    asm("mov.b64 {%0, %1}, %2;" : "=f"(r.x), "=f"(r.y) : "l"(v));
    return r;
}

// ---------------------------------------------------------------------------
// Shared 8x8-microtile mainloop on packed f32x2 FMAs.
// At/Wt are k-major [K][LDSZ] smem tiles (128-wide). ty,tx in [0,16).
// acc[i][jp] holds the (row ty*8+i, cols tx*8+2jp..2jp+1) pair.
// ---------------------------------------------------------------------------
template <int K>
__device__ __forceinline__ void mma8x8(const float* __restrict__ At,
                                       const float* __restrict__ Wt,
                                       int ty, int tx,
                                       unsigned long long acc[8][4]) {
#pragma unroll
    for (int i = 0; i < 8; i++)
#pragma unroll
        for (int jp = 0; jp < 4; jp++) acc[i][jp] = pack2(0.f, 0.f);

    const float* ap = At + ty * 8;
    const float* bp = Wt + tx * 8;
    float4 a0 = *(const float4*)(ap);
    float4 a1 = *(const float4*)(ap + 4);
    float4 b0 = *(const float4*)(bp);
    float4 b1 = *(const float4*)(bp + 4);

#pragma unroll 8
    for (int k = 0; k < K; k++) {
        int kn = (k + 1 < K) ? (k + 1) : k;
        float4 na0 = *(const float4*)(ap + kn * LDSZ);
        float4 na1 = *(const float4*)(ap + kn * LDSZ + 4);
        float4 nb0 = *(const float4*)(bp + kn * LDSZ);
        float4 nb1 = *(const float4*)(bp + kn * LDSZ + 4);

        unsigned long long bq[4];
        bq[0] = pack2(b0.x, b0.y); bq[1] = pack2(b0.z, b0.w);
        bq[2] = pack2(b1.x, b1.y); bq[3] = pack2(b1.z, b1.w);
        float av[8] = {a0.x, a0.y, a0.z, a0.w, a1.x, a1.y, a1.z, a1.w};
#pragma unroll
        for (int i = 0; i < 8; i++) {
            unsigned long long aq = pack2(av[i], av[i]);
#pragma unroll
            for (int jp = 0; jp < 4; jp++) ffma2(acc[i][jp], aq, bq[jp]);
        }
        a0 = na0; a1 = na1; b0 = nb0; b1 = nb1;
    }
}

// ---------------------------------------------------------------------------
// Node GEMM: C[M x Nout] = act(A[M x K] @ W[Nout x K]^T + bias)
// BM=128, BN=128, 256 threads, 8x8 microtile. ACT: 0=none, 1=leaky_relu.
// ---------------------------------------------------------------------------
template <int K, int ACT>
__global__ __launch_bounds__(256, 1)
void gemm_kernel(const float* __restrict__ A, const float* __restrict__ W,
                 const float* __restrict__ bias, float* __restrict__ C,
                 int M, int Nout) {
    extern __shared__ float sm[];
    float* At = sm;              // [K][LDSZ]
    float* Wt = sm + K * LDSZ;   // [K][LDSZ]

    const int tid = threadIdx.x;
    const int m0 = blockIdx.y * 128;
    const int n0 = blockIdx.x * 128;
    constexpr int KC = K / 4;

    for (int idx = tid; idx < 128 * KC; idx += 256) {
        int row = idx / KC;
        int kc = (idx % KC) * 4;
        float4 v = make_float4(0.f, 0.f, 0.f, 0.f);
        if (m0 + row < M) v = *(const float4*)(A + (size_t)(m0 + row) * K + kc);
        At[(kc + 0) * LDSZ + row] = v.x;
        At[(kc + 1) * LDSZ + row] = v.y;
        At[(kc + 2) * LDSZ + row] = v.z;
        At[(kc + 3) * LDSZ + row] = v.w;
    }
    for (int idx = tid; idx < 128 * KC; idx += 256) {
        int row = idx / KC;
        int kc = (idx % KC) * 4;
        float4 v = *(const float4*)(W + (size_t)(n0 + row) * K + kc);
        Wt[(kc + 0) * LDSZ + row] = v.x;
        Wt[(kc + 1) * LDSZ + row] = v.y;
        Wt[(kc + 2) * LDSZ + row] = v.z;
        Wt[(kc + 3) * LDSZ + row] = v.w;
    }
    __syncthreads();

    const int ty = tid >> 4, tx = tid & 15;
    unsigned long long acc[8][4];
    mma8x8<K>(At, Wt, ty, tx, acc);

    float2 bv[4];
#pragma unroll
    for (int jp = 0; jp < 4; jp++) bv[jp] = *(const float2*)(bias + n0 + tx * 8 + jp * 2);

#pragma unroll
    for (int i = 0; i < 8; i++) {
        int row = m0 + ty * 8 + i;
        if (row < M) {
            float o[8];
#pragma unroll
            for (int jp = 0; jp < 4; jp++) {
                float2 f = unpk(acc[i][jp]);
                float v0 = f.x + bv[jp].x;
                float v1 = f.y + bv[jp].y;
                if (ACT == 1) { v0 = lrelu_f(v0); v1 = lrelu_f(v1); }
                o[jp * 2] = v0; o[jp * 2 + 1] = v1;
            }
            float* cp = C + (size_t)row * Nout + n0 + tx * 8;
            *(float4*)cp = make_float4(o[0], o[1], o[2], o[3]);
            *(float4*)(cp + 4) = make_float4(o[4], o[5], o[6], o[7]);
        }
    }
}

// ---------------------------------------------------------------------------
// Edge kernel: per block -> 16 dst nodes = 128 contiguous edges.
//   nn_e  = lrelu(W2 @ cat(atom[src], bond_e) + b2)   (never materialized)
//   logit = lrelu(dot(h1[dst], Ww[:128]) + dot(nn_e, Ww[128:]) + bw)
//   score = softmax over 8 edges/node; ctx = elu(sum score*nt[src])
// GEMM part: [128 edges x 192] @ W2^T[192 x 128], 8x8 microtile, f32x2 FMA.
// ---------------------------------------------------------------------------
__global__ __launch_bounds__(256, 1)
void edge_kernel(const float* __restrict__ atom, const float* __restrict__ bond,
                 const int* __restrict__ src, const float* __restrict__ h1,
                 const float* __restrict__ W2, const float* __restrict__ b2,
                 const float* __restrict__ Ww, const float* __restrict__ bw,
                 const float* __restrict__ nt, float* __restrict__ ctx) {
    extern __shared__ float sm[];
    float* Wt    = sm;                    // [192][LDSZ]
    float* Xt    = Wt + 192 * LDSZ;       // [192][LDSZ]
    float* slog  = Xt + 192 * LDSZ;       // [128]
    float* sscr  = slog + 128;            // [128]
    float* sndot = sscr + 128;            // [16]
    int*   ssrc  = (int*)(sndot + 16);    // [128]

    const int tid = threadIdx.x;
    const int nb = blockIdx.x * 16;
    const long eb = (long)blockIdx.x * 128;

    if (tid < 128) ssrc[tid] = src[eb + tid];
    __syncthreads();

    // stage W2 [128][192] transposed -> Wt[k][j]
    for (int idx = tid; idx < 128 * 48; idx += 256) {
        int j = idx / 48;
        int kc = (idx % 48) * 4;
        float4 v = *(const float4*)(W2 + (size_t)j * 192 + kc);
        Wt[(kc + 0) * LDSZ + j] = v.x;
        Wt[(kc + 1) * LDSZ + j] = v.y;
        Wt[(kc + 2) * LDSZ + j] = v.z;
        Wt[(kc + 3) * LDSZ + j] = v.w;
    }
    // stage gathered edge inputs transposed -> Xt[k][e]
    for (int idx = tid; idx < 128 * 48; idx += 256) {
        int e = idx / 48;
        int kc = (idx % 48) * 4;
        float4 v;
        if (kc < 128) v = *(const float4*)(atom + (size_t)ssrc[e] * 128 + kc);
        else          v = *(const float4*)(bond + (size_t)(eb + e) * 64 + (kc - 128));
        Xt[(kc + 0) * LDSZ + e] = v.x;
        Xt[(kc + 1) * LDSZ + e] = v.y;
        Xt[(kc + 2) * LDSZ + e] = v.z;
        Xt[(kc + 3) * LDSZ + e] = v.w;
    }
    // per-node h1 . Ww[0:128] + bw : 16 lanes per node
    {
        int g = tid >> 4, l = tid & 15;
        const float* hr = h1 + (size_t)(nb + g) * 128;
        float s = 0.f;
#pragma unroll
        for (int t = 0; t < 8; t++) s += hr[l + 16 * t] * Ww[l + 16 * t];
        s += __shfl_xor_sync(0xffffffffu, s, 1);
        s += __shfl_xor_sync(0xffffffffu, s, 2);
        s += __shfl_xor_sync(0xffffffffu, s, 4);
        s += __shfl_xor_sync(0xffffffffu, s, 8);
        if (l == 0) sndot[g] = s + bw[0];
    }
    __syncthreads();

    const int ty = tid >> 4, tx = tid & 15;
    unsigned long long acc[8][4];
    mma8x8<192>(Xt, Wt, ty, tx, acc);

    // fold nn_e -> logit contribution, reduce across the 16 tx lanes
    float2 b2v[4], wwv[4];
#pragma unroll
    for (int jp = 0; jp < 4; jp++) {
        b2v[jp] = *(const float2*)(b2 + tx * 8 + jp * 2);
        wwv[jp] = *(const float2*)(Ww + 128 + tx * 8 + jp * 2);
    }
#pragma unroll
    for (int i = 0; i < 8; i++) {
        float s = 0.f;
#pragma unroll
        for (int jp = 0; jp < 4; jp++) {
            float2 f = unpk(acc[i][jp]);
            s += lrelu_f(f.x + b2v[jp].x) * wwv[jp].x;
            s += lrelu_f(f.y + b2v[jp].y) * wwv[jp].y;
        }
        s += __shfl_xor_sync(0xffffffffu, s, 1);
        s += __shfl_xor_sync(0xffffffffu, s, 2);
        s += __shfl_xor_sync(0xffffffffu, s, 4);
        s += __shfl_xor_sync(0xffffffffu, s, 8);
        if (tx == 0) slog[ty * 8 + i] = s;
    }
    __syncthreads();

    // per-node softmax over 8 edges
    if (tid < 16) {
        float base = sndot[tid];
        float l[8];
        float m = -1e30f;
#pragma unroll
        for (int e = 0; e < 8; e++) {
            float v = lrelu_f(slog[tid * 8 + e] + base);
            l[e] = v;
            m = fmaxf(m, v);
        }
        float ssum = 0.f;
#pragma unroll
        for (int e = 0; e < 8; e++) { l[e] = expf(l[e] - m); ssum += l[e]; }
        float inv = 1.f / ssum;
#pragma unroll
        for (int e = 0; e < 8; e++) sscr[tid * 8 + e] = l[e] * inv;
    }
    __syncthreads();

    // weighted gather of nt[src], elu, store ctx: 32 lanes/node, 2 phases
#pragma unroll
    for (int ph = 0; ph < 2; ph++) {
        int g = (tid >> 5) + ph * 8;
        int lane = tid & 31;
        float c0 = 0.f, c1 = 0.f, c2 = 0.f, c3 = 0.f;
#pragma unroll
        for (int e = 0; e < 8; e++) {
            const float* r = nt + (size_t)ssrc[g * 8 + e] * 128;
            float sc = sscr[g * 8 + e];
            c0 += sc * r[lane];
            c1 += sc * r[lane + 32];
            c2 += sc * r[lane + 64];
            c3 += sc * r[lane + 96];
        }
        c0 = c0 > 0.f ? c0 : (expf(c0) - 1.f);
        c1 = c1 > 0.f ? c1 : (expf(c1) - 1.f);
        c2 = c2 > 0.f ? c2 : (expf(c2) - 1.f);
        c3 = c3 > 0.f ? c3 : (expf(c3) - 1.f);
        float* o = ctx + (size_t)(nb + g) * 128;
        o[lane] = c0;
        o[lane + 32] = c1;
        o[lane + 64] = c2;
        o[lane + 96] = c3;
    }
}

// ---------------------------------------------------------------------------
// GRU elementwise combine (float4-vectorized)
// ---------------------------------------------------------------------------
__global__ __launch_bounds__(256)
void gru_combine(const float* __restrict__ gi, const float* __restrict__ gh,
                 const float* __restrict__ h1, float* __restrict__ out) {
    int i = blockIdx.x * blockDim.x + threadIdx.x;   // float4 index
    if (i >= NN * 32) return;
    int n = i >> 5, q = i & 31;
    const float4* gi4 = (const float4*)gi + (size_t)n * 96;
    const float4* gh4 = (const float4*)gh + (size_t)n * 96;
    float4 ir = gi4[q], iz = gi4[q + 32], in = gi4[q + 64];
    float4 hr = gh4[q], hz = gh4[q + 32], hn = gh4[q + 64];
    float4 h  = ((const float4*)h1)[(size_t)n * 32 + q];
    float4 o;
    {
        float r = 1.f / (1.f + expf(-(ir.x + hr.x)));
        float z = 1.f / (1.f + expf(-(iz.x + hz.x)));
        float nv = tanhf(in.x + r * hn.x);
        o.x = (1.f - z) * nv + z * h.x;
    }
    {
        float r = 1.f / (1.f + expf(-(ir.y + hr.y)));
        float z = 1.f / (1.f + expf(-(iz.y + hz.y)));
        float nv = tanhf(in.y + r * hn.y);
        o.y = (1.f - z) * nv + z * h.y;
    }
    {
        float r = 1.f / (1.f + expf(-(ir.z + hr.z)));
        float z = 1.f / (1.f + expf(-(iz.z + hz.z)));
        float nv = tanhf(in.z + r * hn.z);
        o.z = (1.f - z) * nv + z * h.z;
    }
    {
        float r = 1.f / (1.f + expf(-(ir.w + hr.w)));
        float z = 1.f / (1.f + expf(-(iz.w + hz.w)));
        float nv = tanhf(in.w + r * hn.w);
        o.w = (1.f - z) * nv + z * h.w;
    }
    ((float4*)out)[i] = o;
}

// ---------------------------------------------------------------------------
extern "C" void kernel_launch(void* const* d_in, const int* in_sizes, int n_in,
                              void* d_out, int out_size) {
    const float* atom = (const float*)d_in[0];
    const float* bond = (const float*)d_in[1];
    const int*   src  = (const int*)d_in[2];
    // d_in[3] = dst (structurally e/8; unused)
    const float* W1   = (const float*)d_in[4];
    const float* b1   = (const float*)d_in[5];
    const float* W2   = (const float*)d_in[6];
    const float* b2   = (const float*)d_in[7];
    const float* Wa   = (const float*)d_in[8];
    const float* ba   = (const float*)d_in[9];
    const float* Ww   = (const float*)d_in[10];
    const float* bw   = (const float*)d_in[11];
    const float* W_ih = (const float*)d_in[12];
    const float* b_ih = (const float*)d_in[13];
    const float* W_hh = (const float*)d_in[14];
    const float* b_hh = (const float*)d_in[15];

    float* out = (float*)d_out;

    float *nt, *ctx, *gi, *gh, *h1fb;
    cudaGetSymbolAddress((void**)&nt,   g_nt);
    cudaGetSymbolAddress((void**)&ctx,  g_ctx);
    cudaGetSymbolAddress((void**)&gi,   g_gi);
    cudaGetSymbolAddress((void**)&gh,   g_gh);
    cudaGetSymbolAddress((void**)&h1fb, g_h1);

    float* h1 = (out_size >= 2 * NN * 128) ? (out + (size_t)NN * 128) : h1fb;

    const int GSM = 2 * 128 * LDSZ * sizeof(float);                       // 135168 B
    const int ESM = (2 * 192 * LDSZ + 128 + 128 + 16) * 4 + 128 * 4;      // ~204 KB

    cudaFuncSetAttribute(gemm_kernel<128, 1>, cudaFuncAttributeMaxDynamicSharedMemorySize, GSM);
    cudaFuncSetAttribute(gemm_kernel<128, 0>, cudaFuncAttributeMaxDynamicSharedMemorySize, GSM);
    cudaFuncSetAttribute(edge_kernel, cudaFuncAttributeMaxDynamicSharedMemorySize, ESM);

    const int MB = (NN + 127) / 128;  // 782

    // 1) h1 = lrelu(atom @ W1^T + b1)
    gemm_kernel<128, 1><<<dim3(1, MB), 256, GSM>>>(atom, W1, b1, h1, NN, 128);
    // 2) nt = h1 @ Wa^T + ba
    gemm_kernel<128, 0><<<dim3(1, MB), 256, GSM>>>(h1, Wa, ba, nt, NN, 128);
    // 3) fused edge kernel -> context
    edge_kernel<<<NN / 16, 256, ESM>>>(atom, bond, src, h1, W2, b2, Ww, bw, nt, ctx);
    // 4) GRU input/hidden GEMMs
    gemm_kernel<128, 0><<<dim3(3, MB), 256, GSM>>>(ctx, W_ih, b_ih, gi, NN, 384);
    gemm_kernel<128, 0><<<dim3(3, MB), 256, GSM>>>(h1, W_hh, b_hh, gh, NN, 384);
    // 5) combine -> final
    gru_combine<<<(NN * 32 + 255) / 256, 256>>>(gi, gh, h1, out);
}

// round 4
// speedup vs baseline: 2.0545x; 1.4565x over previous
#include <cuda_runtime.h>
#include <math.h>

#define NN 100000
#define LEAKY 0.2f

constexpr int LDSZ = 132;   // 128 + 4 pad
constexpr int BK   = 64;    // k-chunk

// ---------------- scratch (device globals; no allocation allowed) ----------
__device__ float g_nt [(size_t)NN * 128];
__device__ float g_ctx[(size_t)NN * 128];
__device__ float g_h1 [(size_t)NN * 128];
__device__ float g_gi [(size_t)NN * 384];
__device__ float g_gh [(size_t)NN * 384];

__device__ __forceinline__ float lrelu_f(float x) { return x > 0.f ? x : LEAKY * x; }

__device__ __forceinline__ unsigned long long pack2(float lo, float hi) {
    unsigned long long r;
    asm("mov.b64 %0, {%1, %2};" : "=l"(r) : "f"(lo), "f"(hi));
    return r;
}
__device__ __forceinline__ void ffma2(unsigned long long& d, unsigned long long a, unsigned long long b) {
    asm("fma.rn.f32x2 %0, %1, %2, %0;" : "+l"(d) : "l"(a), "l"(b));
}
__device__ __forceinline__ float2 unpk(unsigned long long v) {
    float2 r;
    asm("mov.b64 {%0, %1}, %2;" : "=f"(r.x), "=f"(r.y) : "l"(v));
    return r;
}

// ---------------------------------------------------------------------------
// One BK-wide chunk of the 8x8-microtile f32x2 mainloop.
// At/Wt: k-major [BK][LDSZ] smem tiles. acc accumulates across chunks.
// ---------------------------------------------------------------------------
__device__ __forceinline__ void mma_chunk(const float* __restrict__ At,
                                          const float* __restrict__ Wt,
                                          int ty, int tx,
                                          unsigned long long acc[8][4]) {
    const float* ap = At + ty * 8;
    const float* bp = Wt + tx * 8;
    float4 a0 = *(const float4*)(ap);
    float4 a1 = *(const float4*)(ap + 4);
    float4 b0 = *(const float4*)(bp);
    float4 b1 = *(const float4*)(bp + 4);

#pragma unroll 8
    for (int k = 0; k < BK; k++) {
        int kn = (k + 1 < BK) ? (k + 1) : k;
        float4 na0 = *(const float4*)(ap + kn * LDSZ);
        float4 na1 = *(const float4*)(ap + kn * LDSZ + 4);
        float4 nb0 = *(const float4*)(bp + kn * LDSZ);
        float4 nb1 = *(const float4*)(bp + kn * LDSZ + 4);

        unsigned long long bq[4];
        bq[0] = pack2(b0.x, b0.y); bq[1] = pack2(b0.z, b0.w);
        bq[2] = pack2(b1.x, b1.y); bq[3] = pack2(b1.z, b1.w);
        float av[8] = {a0.x, a0.y, a0.z, a0.w, a1.x, a1.y, a1.z, a1.w};
#pragma unroll
        for (int i = 0; i < 8; i++) {
            unsigned long long aq = pack2(av[i], av[i]);
#pragma unroll
            for (int jp = 0; jp < 4; jp++) ffma2(acc[i][jp], aq, bq[jp]);
        }
        a0 = na0; a1 = na1; b0 = nb0; b1 = nb1;
    }
}

// ---------------------------------------------------------------------------
// Node GEMM: C[M x Nout] = act(A[M x K] @ W[Nout x K]^T + bias)
// BM=128, BN=128, BK=64 chunks, 256 threads, 8x8 microtile, 2 CTAs/SM.
// ---------------------------------------------------------------------------
template <int K, int ACT>
__global__ __launch_bounds__(256, 2)
void gemm_kernel(const float* __restrict__ A, const float* __restrict__ W,
                 const float* __restrict__ bias, float* __restrict__ C,
                 int M, int Nout) {
    extern __shared__ float sm[];
    float* At = sm;               // [BK][LDSZ]
    float* Wt = sm + BK * LDSZ;   // [BK][LDSZ]

    const int tid = threadIdx.x;
    const int m0 = blockIdx.y * 128;
    const int n0 = blockIdx.x * 128;
    const int ty = tid >> 4, tx = tid & 15;

    unsigned long long acc[8][4];
#pragma unroll
    for (int i = 0; i < 8; i++)
#pragma unroll
        for (int jp = 0; jp < 4; jp++) acc[i][jp] = pack2(0.f, 0.f);

#pragma unroll
    for (int c = 0; c < K / BK; c++) {
        if (c) __syncthreads();
        // stage A chunk (transposed)
        for (int idx = tid; idx < 128 * (BK / 4); idx += 256) {
            int row = idx / (BK / 4);
            int kc = (idx % (BK / 4)) * 4;
            float4 v = make_float4(0.f, 0.f, 0.f, 0.f);
            if (m0 + row < M) v = *(const float4*)(A + (size_t)(m0 + row) * K + c * BK + kc);
            At[(kc + 0) * LDSZ + row] = v.x;
            At[(kc + 1) * LDSZ + row] = v.y;
            At[(kc + 2) * LDSZ + row] = v.z;
            At[(kc + 3) * LDSZ + row] = v.w;
        }
        // stage W chunk (transposed)
        for (int idx = tid; idx < 128 * (BK / 4); idx += 256) {
            int row = idx / (BK / 4);
            int kc = (idx % (BK / 4)) * 4;
            float4 v = *(const float4*)(W + (size_t)(n0 + row) * K + c * BK + kc);
            Wt[(kc + 0) * LDSZ + row] = v.x;
            Wt[(kc + 1) * LDSZ + row] = v.y;
            Wt[(kc + 2) * LDSZ + row] = v.z;
            Wt[(kc + 3) * LDSZ + row] = v.w;
        }
        __syncthreads();
        mma_chunk(At, Wt, ty, tx, acc);
    }

    float2 bv[4];
#pragma unroll
    for (int jp = 0; jp < 4; jp++) bv[jp] = *(const float2*)(bias + n0 + tx * 8 + jp * 2);

#pragma unroll
    for (int i = 0; i < 8; i++) {
        int row = m0 + ty * 8 + i;
        if (row < M) {
            float o[8];
#pragma unroll
            for (int jp = 0; jp < 4; jp++) {
                float2 f = unpk(acc[i][jp]);
                float v0 = f.x + bv[jp].x;
                float v1 = f.y + bv[jp].y;
                if (ACT == 1) { v0 = lrelu_f(v0); v1 = lrelu_f(v1); }
                o[jp * 2] = v0; o[jp * 2 + 1] = v1;
            }
            float* cp = C + (size_t)row * Nout + n0 + tx * 8;
            *(float4*)cp = make_float4(o[0], o[1], o[2], o[3]);
            *(float4*)(cp + 4) = make_float4(o[4], o[5], o[6], o[7]);
        }
    }
}

// ---------------------------------------------------------------------------
// Edge kernel: per block -> 16 dst nodes = 128 contiguous edges.
//   nn_e  = lrelu(W2 @ cat(atom[src], bond_e) + b2)   (never materialized)
//   logit = lrelu(dot(h1[dst], Ww[:128]) + dot(nn_e, Ww[128:]) + bw)
//   score = softmax over 8 edges/node; ctx = elu(sum score*nt[src])
// GEMM part: [128 x 128 x 192] in 3 BK=64 chunks, 2 CTAs/SM.
// ---------------------------------------------------------------------------
__global__ __launch_bounds__(256, 2)
void edge_kernel(const float* __restrict__ atom, const float* __restrict__ bond,
                 const int* __restrict__ src, const float* __restrict__ h1,
                 const float* __restrict__ W2, const float* __restrict__ b2,
                 const float* __restrict__ Ww, const float* __restrict__ bw,
                 const float* __restrict__ nt, float* __restrict__ ctx) {
    extern __shared__ float sm[];
    float* Xt    = sm;                    // [BK][LDSZ]
    float* Wt    = sm + BK * LDSZ;        // [BK][LDSZ]
    float* slog  = Wt + BK * LDSZ;        // [128]
    float* sscr  = slog + 128;            // [128]
    float* sndot = sscr + 128;            // [16]
    int*   ssrc  = (int*)(sndot + 16);    // [128]

    const int tid = threadIdx.x;
    const int nb = blockIdx.x * 16;
    const long eb = (long)blockIdx.x * 128;
    const int ty = tid >> 4, tx = tid & 15;

    if (tid < 128) ssrc[tid] = src[eb + tid];

    // per-node h1 . Ww[0:128] + bw : 16 lanes per node
    {
        int g = tid >> 4, l = tid & 15;
        const float* hr = h1 + (size_t)(nb + g) * 128;
        float s = 0.f;
#pragma unroll
        for (int t = 0; t < 8; t++) s += hr[l + 16 * t] * Ww[l + 16 * t];
        s += __shfl_xor_sync(0xffffffffu, s, 1);
        s += __shfl_xor_sync(0xffffffffu, s, 2);
        s += __shfl_xor_sync(0xffffffffu, s, 4);
        s += __shfl_xor_sync(0xffffffffu, s, 8);
        if (l == 0) sndot[g] = s + bw[0];
    }
    __syncthreads();

    unsigned long long acc[8][4];
#pragma unroll
    for (int i = 0; i < 8; i++)
#pragma unroll
        for (int jp = 0; jp < 4; jp++) acc[i][jp] = pack2(0.f, 0.f);

#pragma unroll
    for (int c = 0; c < 3; c++) {
        if (c) __syncthreads();
        // stage W2 chunk transposed: Wt[k][j], k = c*64 + kc
        for (int idx = tid; idx < 128 * 16; idx += 256) {
            int j = idx / 16;
            int kc = (idx % 16) * 4;
            float4 v = *(const float4*)(W2 + (size_t)j * 192 + c * BK + kc);
            Wt[(kc + 0) * LDSZ + j] = v.x;
            Wt[(kc + 1) * LDSZ + j] = v.y;
            Wt[(kc + 2) * LDSZ + j] = v.z;
            Wt[(kc + 3) * LDSZ + j] = v.w;
        }
        // stage edge-input chunk transposed: Xt[k][e]
        for (int idx = tid; idx < 128 * 16; idx += 256) {
            int e = idx / 16;
            int kc = (idx % 16) * 4;
            float4 v;
            if (c < 2) v = *(const float4*)(atom + (size_t)ssrc[e] * 128 + c * BK + kc);
            else       v = *(const float4*)(bond + (size_t)(eb + e) * 64 + kc);
            Xt[(kc + 0) * LDSZ + e] = v.x;
            Xt[(kc + 1) * LDSZ + e] = v.y;
            Xt[(kc + 2) * LDSZ + e] = v.z;
            Xt[(kc + 3) * LDSZ + e] = v.w;
        }
        __syncthreads();
        mma_chunk(Xt, Wt, ty, tx, acc);
    }

    // fold nn_e -> logit contribution, reduce across the 16 tx lanes
    float2 b2v[4], wwv[4];
#pragma unroll
    for (int jp = 0; jp < 4; jp++) {
        b2v[jp] = *(const float2*)(b2 + tx * 8 + jp * 2);
        wwv[jp] = *(const float2*)(Ww + 128 + tx * 8 + jp * 2);
    }
#pragma unroll
    for (int i = 0; i < 8; i++) {
        float s = 0.f;
#pragma unroll
        for (int jp = 0; jp < 4; jp++) {
            float2 f = unpk(acc[i][jp]);
            s += lrelu_f(f.x + b2v[jp].x) * wwv[jp].x;
            s += lrelu_f(f.y + b2v[jp].y) * wwv[jp].y;
        }
        s += __shfl_xor_sync(0xffffffffu, s, 1);
        s += __shfl_xor_sync(0xffffffffu, s, 2);
        s += __shfl_xor_sync(0xffffffffu, s, 4);
        s += __shfl_xor_sync(0xffffffffu, s, 8);
        if (tx == 0) slog[ty * 8 + i] = s;
    }
    __syncthreads();

    // per-node softmax over 8 edges
    if (tid < 16) {
        float base = sndot[tid];
        float l[8];
        float m = -1e30f;
#pragma unroll
        for (int e = 0; e < 8; e++) {
            float v = lrelu_f(slog[tid * 8 + e] + base);
            l[e] = v;
            m = fmaxf(m, v);
        }
        float ssum = 0.f;
#pragma unroll
        for (int e = 0; e < 8; e++) { l[e] = expf(l[e] - m); ssum += l[e]; }
        float inv = 1.f / ssum;
#pragma unroll
        for (int e = 0; e < 8; e++) sscr[tid * 8 + e] = l[e] * inv;
    }
    __syncthreads();

    // weighted gather of nt[src], elu, store ctx: 32 lanes/node, 2 phases
#pragma unroll
    for (int ph = 0; ph < 2; ph++) {
        int g = (tid >> 5) + ph * 8;
        int lane = tid & 31;
        float c0 = 0.f, c1 = 0.f, c2 = 0.f, c3 = 0.f;
#pragma unroll
        for (int e = 0; e < 8; e++) {
            const float* r = nt + (size_t)ssrc[g * 8 + e] * 128;
            float sc = sscr[g * 8 + e];
            c0 += sc * r[lane];
            c1 += sc * r[lane + 32];
            c2 += sc * r[lane + 64];
            c3 += sc * r[lane + 96];
        }
        c0 = c0 > 0.f ? c0 : (expf(c0) - 1.f);
        c1 = c1 > 0.f ? c1 : (expf(c1) - 1.f);
        c2 = c2 > 0.f ? c2 : (expf(c2) - 1.f);
        c3 = c3 > 0.f ? c3 : (expf(c3) - 1.f);
        float* o = ctx + (size_t)(nb + g) * 128;
        o[lane] = c0;
        o[lane + 32] = c1;
        o[lane + 64] = c2;
        o[lane + 96] = c3;
    }
}

// ---------------------------------------------------------------------------
// GRU elementwise combine (float4-vectorized)
// ---------------------------------------------------------------------------
__global__ __launch_bounds__(256)
void gru_combine(const float* __restrict__ gi, const float* __restrict__ gh,
                 const float* __restrict__ h1, float* __restrict__ out) {
    int i = blockIdx.x * blockDim.x + threadIdx.x;   // float4 index
    if (i >= NN * 32) return;
    int n = i >> 5, q = i & 31;
    const float4* gi4 = (const float4*)gi + (size_t)n * 96;
    const float4* gh4 = (const float4*)gh + (size_t)n * 96;
    float4 ir = gi4[q], iz = gi4[q + 32], in = gi4[q + 64];
    float4 hr = gh4[q], hz = gh4[q + 32], hn = gh4[q + 64];
    float4 h  = ((const float4*)h1)[(size_t)n * 32 + q];
    float4 o;
    {
        float r = 1.f / (1.f + expf(-(ir.x + hr.x)));
        float z = 1.f / (1.f + expf(-(iz.x + hz.x)));
        float nv = tanhf(in.x + r * hn.x);
        o.x = (1.f - z) * nv + z * h.x;
    }
    {
        float r = 1.f / (1.f + expf(-(ir.y + hr.y)));
        float z = 1.f / (1.f + expf(-(iz.y + hz.y)));
        float nv = tanhf(in.y + r * hn.y);
        o.y = (1.f - z) * nv + z * h.y;
    }
    {
        float r = 1.f / (1.f + expf(-(ir.z + hr.z)));
        float z = 1.f / (1.f + expf(-(iz.z + hz.z)));
        float nv = tanhf(in.z + r * hn.z);
        o.z = (1.f - z) * nv + z * h.z;
    }
    {
        float r = 1.f / (1.f + expf(-(ir.w + hr.w)));
        float z = 1.f / (1.f + expf(-(iz.w + hz.w)));
        float nv = tanhf(in.w + r * hn.w);
        o.w = (1.f - z) * nv + z * h.w;
    }
    ((float4*)out)[i] = o;
}

// ---------------------------------------------------------------------------
extern "C" void kernel_launch(void* const* d_in, const int* in_sizes, int n_in,
                              void* d_out, int out_size) {
    const float* atom = (const float*)d_in[0];
    const float* bond = (const float*)d_in[1];
    const int*   src  = (const int*)d_in[2];
    // d_in[3] = dst (structurally e/8; unused)
    const float* W1   = (const float*)d_in[4];
    const float* b1   = (const float*)d_in[5];
    const float* W2   = (const float*)d_in[6];
    const float* b2   = (const float*)d_in[7];
    const float* Wa   = (const float*)d_in[8];
    const float* ba   = (const float*)d_in[9];
    const float* Ww   = (const float*)d_in[10];
    const float* bw   = (const float*)d_in[11];
    const float* W_ih = (const float*)d_in[12];
    const float* b_ih = (const float*)d_in[13];
    const float* W_hh = (const float*)d_in[14];
    const float* b_hh = (const float*)d_in[15];

    float* out = (float*)d_out;

    float *nt, *ctx, *gi, *gh, *h1fb;
    cudaGetSymbolAddress((void**)&nt,   g_nt);
    cudaGetSymbolAddress((void**)&ctx,  g_ctx);
    cudaGetSymbolAddress((void**)&gi,   g_gi);
    cudaGetSymbolAddress((void**)&gh,   g_gh);
    cudaGetSymbolAddress((void**)&h1fb, g_h1);

    float* h1 = (out_size >= 2 * NN * 128) ? (out + (size_t)NN * 128) : h1fb;

    const int GSM = 2 * BK * LDSZ * sizeof(float);                        // 67584 B
    const int ESM = (2 * BK * LDSZ + 128 + 128 + 16) * 4 + 128 * 4;       // ~68.7 KB

    cudaFuncSetAttribute(gemm_kernel<128, 1>, cudaFuncAttributeMaxDynamicSharedMemorySize, GSM);
    cudaFuncSetAttribute(gemm_kernel<128, 0>, cudaFuncAttributeMaxDynamicSharedMemorySize, GSM);
    cudaFuncSetAttribute(edge_kernel, cudaFuncAttributeMaxDynamicSharedMemorySize, ESM);

    const int MB = (NN + 127) / 128;  // 782

    // 1) h1 = lrelu(atom @ W1^T + b1)
    gemm_kernel<128, 1><<<dim3(1, MB), 256, GSM>>>(atom, W1, b1, h1, NN, 128);
    // 2) nt = h1 @ Wa^T + ba
    gemm_kernel<128, 0><<<dim3(1, MB), 256, GSM>>>(h1, Wa, ba, nt, NN, 128);
    // 3) fused edge kernel -> context
    edge_kernel<<<NN / 16, 256, ESM>>>(atom, bond, src, h1, W2, b2, Ww, bw, nt, ctx);
    // 4) GRU input/hidden GEMMs
    gemm_kernel<128, 0><<<dim3(3, MB), 256, GSM>>>(ctx, W_ih, b_ih, gi, NN, 384);
    gemm_kernel<128, 0><<<dim3(3, MB), 256, GSM>>>(h1, W_hh, b_hh, gh, NN, 384);
    // 5) combine -> final
    gru_combine<<<(NN * 32 + 255) / 256, 256>>>(gi, gh, h1, out);
}

// round 6
// speedup vs baseline: 4.8658x; 2.3684x over previous
#include <cuda_runtime.h>
#include <math.h>
#include <stdint.h>

#define NN 100000
#define LEAKY 0.2f

constexpr int BK   = 64;
constexpr int LDK  = 68;    // smem row stride (floats) for [row][k] chunk tiles

// ---------------- scratch (device globals; no allocation allowed) -----------
__device__ float g_nt [(size_t)NN * 128];
__device__ float g_ctx[(size_t)NN * 128];
__device__ float g_h1 [(size_t)NN * 128];
__device__ float g_gi [(size_t)NN * 384];
__device__ float g_gh [(size_t)NN * 384];

__device__ __forceinline__ float lrelu_f(float x) { return x > 0.f ? x : LEAKY * x; }

__device__ __forceinline__ uint32_t f2tf(float f) {
    uint32_t r;
    asm("cvt.rna.tf32.f32 %0, %1;" : "=r"(r) : "f"(f));
    return r;
}

__device__ __forceinline__ void mma_tf32(float c[4], uint32_t a0, uint32_t a1,
                                         uint32_t a2, uint32_t a3,
                                         uint32_t b0, uint32_t b1) {
    asm volatile(
        "mma.sync.aligned.m16n8k8.row.col.f32.tf32.tf32.f32 "
        "{%0,%1,%2,%3}, {%4,%5,%6,%7}, {%8,%9}, {%0,%1,%2,%3};"
        : "+f"(c[0]), "+f"(c[1]), "+f"(c[2]), "+f"(c[3])
        : "r"(a0), "r"(a1), "r"(a2), "r"(a3), "r"(b0), "r"(b1));
}

// ---------------------------------------------------------------------------
// Stage a [128 x BK] chunk (row-major, tf32-rounded) into smem [128][LDK].
// src row i = srcp + i*srcK + koff. rows_valid guards the M edge.
// ---------------------------------------------------------------------------
__device__ __forceinline__ void stage_chunk(uint32_t* __restrict__ dst,
                                            const float* __restrict__ srcp,
                                            int srcK, int koff, int rows_valid) {
    const int tid = threadIdx.x;
    for (int idx = tid; idx < 128 * (BK / 4); idx += 256) {
        int row = idx >> 4;
        int kq  = (idx & 15) * 4;
        float4 v = make_float4(0.f, 0.f, 0.f, 0.f);
        if (row < rows_valid) v = *(const float4*)(srcp + (size_t)row * srcK + koff + kq);
        uint32_t* d = dst + row * LDK + kq;
        d[0] = f2tf(v.x); d[1] = f2tf(v.y); d[2] = f2tf(v.z); d[3] = f2tf(v.w);
    }
}

// ---------------------------------------------------------------------------
// Warp-tile mainloop over one staged BK chunk.
// Warp grid 2(m) x 4(n); per warp: 4 m16 tiles x 4 n8 tiles.
// As: [128][LDK] A rows, Ws: [128][LDK] B rows (W[n][k]).
// ---------------------------------------------------------------------------
__device__ __forceinline__ void mma_chunk_tc(const uint32_t* __restrict__ As,
                                             const uint32_t* __restrict__ Ws,
                                             int wm, int wn, int g, int tg,
                                             float c[4][4][4]) {
#pragma unroll
    for (int ks = 0; ks < BK / 8; ks++) {
        uint32_t a[4][4];
#pragma unroll
        for (int mt = 0; mt < 4; mt++) {
            const uint32_t* ap = As + (wm * 64 + mt * 16 + g) * LDK + ks * 8 + tg;
            a[mt][0] = ap[0];
            a[mt][1] = ap[8 * LDK];
            a[mt][2] = ap[4];
            a[mt][3] = ap[8 * LDK + 4];
        }
        uint32_t b[4][2];
#pragma unroll
        for (int nt = 0; nt < 4; nt++) {
            const uint32_t* bp = Ws + (wn * 32 + nt * 8 + g) * LDK + ks * 8 + tg;
            b[nt][0] = bp[0];
            b[nt][1] = bp[4];
        }
#pragma unroll
        for (int mt = 0; mt < 4; mt++)
#pragma unroll
            for (int nt = 0; nt < 4; nt++)
                mma_tf32(c[mt][nt], a[mt][0], a[mt][1], a[mt][2], a[mt][3],
                         b[nt][0], b[nt][1]);
    }
}

// ---------------------------------------------------------------------------
// Node GEMM (tensor): C[M x Nout] = act(A[M x 128] @ W[Nout x 128]^T + bias)
// BM=128 (blockIdx.y), BN=128 (blockIdx.x), K=128 in 2 BK chunks. 2 CTAs/SM.
// ACT: 0 = none, 1 = leaky_relu
// ---------------------------------------------------------------------------
template <int ACT>
__global__ __launch_bounds__(256, 2)
void tc_gemm(const float* __restrict__ A, const float* __restrict__ W,
             const float* __restrict__ bias, float* __restrict__ C,
             int M, int Nout) {
    extern __shared__ uint32_t smu[];
    uint32_t* As = smu;                 // [128][LDK]
    uint32_t* Ws = smu + 128 * LDK;     // [128][LDK]

    const int tid = threadIdx.x;
    const int m0 = blockIdx.y * 128;
    const int n0 = blockIdx.x * 128;
    const int wid = tid >> 5, lane = tid & 31;
    const int wm = wid >> 2, wn = wid & 3;
    const int g = lane >> 2, tg = lane & 3;

    float c[4][4][4];
#pragma unroll
    for (int mt = 0; mt < 4; mt++)
#pragma unroll
        for (int nt = 0; nt < 4; nt++)
#pragma unroll
            for (int r = 0; r < 4; r++) c[mt][nt][r] = 0.f;

#pragma unroll
    for (int ch = 0; ch < 2; ch++) {
        if (ch) __syncthreads();
        stage_chunk(As, A + (size_t)m0 * 128, 128, ch * BK, M - m0);
        stage_chunk(Ws, W + (size_t)n0 * 128, 128, ch * BK, 128);
        __syncthreads();
        mma_chunk_tc(As, Ws, wm, wn, g, tg, c);
    }

    // epilogue: each thread owns (row, col*2) float2 pairs
#pragma unroll
    for (int mt = 0; mt < 4; mt++) {
        int r0 = m0 + wm * 64 + mt * 16 + g;
#pragma unroll
        for (int nt = 0; nt < 4; nt++) {
            int col = n0 + wn * 32 + nt * 8 + tg * 2;
            float b0 = __ldg(bias + col), b1 = __ldg(bias + col + 1);
            float v0 = c[mt][nt][0] + b0, v1 = c[mt][nt][1] + b1;
            float v2 = c[mt][nt][2] + b0, v3 = c[mt][nt][3] + b1;
            if (ACT == 1) { v0 = lrelu_f(v0); v1 = lrelu_f(v1); v2 = lrelu_f(v2); v3 = lrelu_f(v3); }
            if (r0 < M)     *(float2*)(C + (size_t)r0 * Nout + col)       = make_float2(v0, v1);
            if (r0 + 8 < M) *(float2*)(C + (size_t)(r0 + 8) * Nout + col) = make_float2(v2, v3);
        }
    }
}

// ---------------------------------------------------------------------------
// Edge kernel (tensor GEMM core): per block -> 16 dst nodes = 128 edges.
//   nn_e  = lrelu(W2 @ cat(atom[src], bond_e) + b2)   (never materialized)
//   logit = lrelu(dot(h1[dst], Ww[:128]) + dot(nn_e, Ww[128:]) + bw)
//   score = softmax over 8 edges/node; ctx = elu(sum score*nt[src])
// GEMM: [128 x 128 x 192] via tf32 mma, 3 BK=64 chunks. 2 CTAs/SM.
// ---------------------------------------------------------------------------
__global__ __launch_bounds__(256, 2)
void edge_kernel(const float* __restrict__ atom, const float* __restrict__ bond,
                 const int* __restrict__ src, const float* __restrict__ h1,
                 const float* __restrict__ W2, const float* __restrict__ b2,
                 const float* __restrict__ Ww, const float* __restrict__ bw,
                 const float* __restrict__ nt, float* __restrict__ ctx) {
    extern __shared__ uint32_t smu[];
    uint32_t* Xs   = smu;                          // [128][LDK]
    uint32_t* Ws   = smu + 128 * LDK;              // [128][LDK]
    float* slog    = (float*)(smu + 2 * 128 * LDK);// [128]
    float* sscr    = slog + 128;                   // [128]
    float* sndot   = sscr + 128;                   // [16]
    int*   ssrc    = (int*)(sndot + 16);           // [128]

    const int tid = threadIdx.x;
    const int nb = blockIdx.x * 16;
    const long eb = (long)blockIdx.x * 128;
    const int wid = tid >> 5, lane = tid & 31;
    const int wm = wid >> 2, wn = wid & 3;
    const int g = lane >> 2, tg = lane & 3;

    if (tid < 128) { ssrc[tid] = src[eb + tid]; slog[tid] = 0.f; }

    // per-node h1 . Ww[0:128] + bw : 16 lanes per node
    {
        int gn = tid >> 4, l = tid & 15;
        const float* hr = h1 + (size_t)(nb + gn) * 128;
        float s = 0.f;
#pragma unroll
        for (int t = 0; t < 8; t++) s += hr[l + 16 * t] * Ww[l + 16 * t];
        s += __shfl_xor_sync(0xffffffffu, s, 1);
        s += __shfl_xor_sync(0xffffffffu, s, 2);
        s += __shfl_xor_sync(0xffffffffu, s, 4);
        s += __shfl_xor_sync(0xffffffffu, s, 8);
        if (l == 0) sndot[gn] = s + bw[0];
    }
    __syncthreads();

    float c[4][4][4];
#pragma unroll
    for (int mt = 0; mt < 4; mt++)
#pragma unroll
        for (int ntl = 0; ntl < 4; ntl++)
#pragma unroll
            for (int r = 0; r < 4; r++) c[mt][ntl][r] = 0.f;

#pragma unroll
    for (int ch = 0; ch < 3; ch++) {
        if (ch) __syncthreads();
        // stage X chunk: rows = edges; k<128 -> gathered atom, else bond
        for (int idx = tid; idx < 128 * (BK / 4); idx += 256) {
            int e  = idx >> 4;
            int kq = (idx & 15) * 4;
            float4 v;
            if (ch < 2) v = *(const float4*)(atom + (size_t)ssrc[e] * 128 + ch * BK + kq);
            else        v = *(const float4*)(bond + (size_t)(eb + e) * 64 + kq);
            uint32_t* d = Xs + e * LDK + kq;
            d[0] = f2tf(v.x); d[1] = f2tf(v.y); d[2] = f2tf(v.z); d[3] = f2tf(v.w);
        }
        stage_chunk(Ws, W2, 192, ch * BK, 128);
        __syncthreads();
        mma_chunk_tc(Xs, Ws, wm, wn, g, tg, c);
    }

    // epilogue: fold nn_e into logit; per-thread partials -> quad shfl -> smem atomic
#pragma unroll
    for (int mt = 0; mt < 4; mt++) {
        int r0 = wm * 64 + mt * 16 + g;
        float p0 = 0.f, p1 = 0.f;
#pragma unroll
        for (int ntl = 0; ntl < 4; ntl++) {
            int col = wn * 32 + ntl * 8 + tg * 2;
            float bb0 = __ldg(b2 + col), bb1 = __ldg(b2 + col + 1);
            float w0 = __ldg(Ww + 128 + col), w1 = __ldg(Ww + 128 + col + 1);
            p0 += lrelu_f(c[mt][ntl][0] + bb0) * w0 + lrelu_f(c[mt][ntl][1] + bb1) * w1;
            p1 += lrelu_f(c[mt][ntl][2] + bb0) * w0 + lrelu_f(c[mt][ntl][3] + bb1) * w1;
        }
        p0 += __shfl_xor_sync(0xffffffffu, p0, 1);
        p0 += __shfl_xor_sync(0xffffffffu, p0, 2);
        p1 += __shfl_xor_sync(0xffffffffu, p1, 1);
        p1 += __shfl_xor_sync(0xffffffffu, p1, 2);
        if (tg == 0) {
            atomicAdd(slog + r0, p0);
            atomicAdd(slog + r0 + 8, p1);
        }
    }
    __syncthreads();

    // per-node softmax over 8 edges
    if (tid < 16) {
        float base = sndot[tid];
        float l[8];
        float m = -1e30f;
#pragma unroll
        for (int e = 0; e < 8; e++) {
            float v = lrelu_f(slog[tid * 8 + e] + base);
            l[e] = v;
            m = fmaxf(m, v);
        }
        float ssum = 0.f;
#pragma unroll
        for (int e = 0; e < 8; e++) { l[e] = expf(l[e] - m); ssum += l[e]; }
        float inv = 1.f / ssum;
#pragma unroll
        for (int e = 0; e < 8; e++) sscr[tid * 8 + e] = l[e] * inv;
    }
    __syncthreads();

    // weighted gather of nt[src], elu, store ctx: 32 lanes/node, 2 phases
#pragma unroll
    for (int ph = 0; ph < 2; ph++) {
        int gn = (tid >> 5) + ph * 8;
        int ln = tid & 31;
        float c0 = 0.f, c1 = 0.f, c2 = 0.f, c3 = 0.f;
#pragma unroll
        for (int e = 0; e < 8; e++) {
            const float* r = nt + (size_t)ssrc[gn * 8 + e] * 128;
            float sc = sscr[gn * 8 + e];
            c0 += sc * r[ln];
            c1 += sc * r[ln + 32];
            c2 += sc * r[ln + 64];
            c3 += sc * r[ln + 96];
        }
        c0 = c0 > 0.f ? c0 : (expf(c0) - 1.f);
        c1 = c1 > 0.f ? c1 : (expf(c1) - 1.f);
        c2 = c2 > 0.f ? c2 : (expf(c2) - 1.f);
        c3 = c3 > 0.f ? c3 : (expf(c3) - 1.f);
        float* o = ctx + (size_t)(nb + gn) * 128;
        o[ln] = c0;
        o[ln + 32] = c1;
        o[ln + 64] = c2;
        o[ln + 96] = c3;
    }
}

// ---------------------------------------------------------------------------
// GRU elementwise combine (float4-vectorized)
// ---------------------------------------------------------------------------
__global__ __launch_bounds__(256)
void gru_combine(const float* __restrict__ gi, const float* __restrict__ gh,
                 const float* __restrict__ h1, float* __restrict__ out) {
    int i = blockIdx.x * blockDim.x + threadIdx.x;   // float4 index
    if (i >= NN * 32) return;
    int n = i >> 5, q = i & 31;
    const float4* gi4 = (const float4*)gi + (size_t)n * 96;
    const float4* gh4 = (const float4*)gh + (size_t)n * 96;
    float4 ir = gi4[q], iz = gi4[q + 32], in = gi4[q + 64];
    float4 hr = gh4[q], hz = gh4[q + 32], hn = gh4[q + 64];
    float4 h  = ((const float4*)h1)[(size_t)n * 32 + q];
    float4 o;
    {
        float r = 1.f / (1.f + expf(-(ir.x + hr.x)));
        float z = 1.f / (1.f + expf(-(iz.x + hz.x)));
        float nv = tanhf(in.x + r * hn.x);
        o.x = (1.f - z) * nv + z * h.x;
    }
    {
        float r = 1.f / (1.f + expf(-(ir.y + hr.y)));
        float z = 1.f / (1.f + expf(-(iz.y + hz.y)));
        float nv = tanhf(in.y + r * hn.y);
        o.y = (1.f - z) * nv + z * h.y;
    }
    {
        float r = 1.f / (1.f + expf(-(ir.z + hr.z)));
        float z = 1.f / (1.f + expf(-(iz.z + hz.z)));
        float nv = tanhf(in.z + r * hn.z);
        o.z = (1.f - z) * nv + z * h.z;
    }
    {
        float r = 1.f / (1.f + expf(-(ir.w + hr.w)));
        float z = 1.f / (1.f + expf(-(iz.w + hz.w)));
        float nv = tanhf(in.w + r * hn.w);
        o.w = (1.f - z) * nv + z * h.w;
    }
    ((float4*)out)[i] = o;
}

// ---------------------------------------------------------------------------
extern "C" void kernel_launch(void* const* d_in, const int* in_sizes, int n_in,
                              void* d_out, int out_size) {
    const float* atom = (const float*)d_in[0];
    const float* bond = (const float*)d_in[1];
    const int*   src  = (const int*)d_in[2];
    // d_in[3] = dst (structurally e/8; unused)
    const float* W1   = (const float*)d_in[4];
    const float* b1   = (const float*)d_in[5];
    const float* W2   = (const float*)d_in[6];
    const float* b2   = (const float*)d_in[7];
    const float* Wa   = (const float*)d_in[8];
    const float* ba   = (const float*)d_in[9];
    const float* Ww   = (const float*)d_in[10];
    const float* bw   = (const float*)d_in[11];
    const float* W_ih = (const float*)d_in[12];
    const float* b_ih = (const float*)d_in[13];
    const float* W_hh = (const float*)d_in[14];
    const float* b_hh = (const float*)d_in[15];

    float* out = (float*)d_out;

    float *nt, *ctx, *gi, *gh, *h1fb;
    cudaGetSymbolAddress((void**)&nt,   g_nt);
    cudaGetSymbolAddress((void**)&ctx,  g_ctx);
    cudaGetSymbolAddress((void**)&gi,   g_gi);
    cudaGetSymbolAddress((void**)&gh,   g_gh);
    cudaGetSymbolAddress((void**)&h1fb, g_h1);

    float* h1 = (out_size >= 2 * NN * 128) ? (out + (size_t)NN * 128) : h1fb;

    const int GSM = 2 * 128 * LDK * sizeof(float);                        // 69632 B
    const int ESM = GSM + (128 + 128 + 16) * 4 + 128 * 4;                 // ~70.8 KB

    cudaFuncSetAttribute(tc_gemm<1>, cudaFuncAttributeMaxDynamicSharedMemorySize, GSM);
    cudaFuncSetAttribute(tc_gemm<0>, cudaFuncAttributeMaxDynamicSharedMemorySize, GSM);
    cudaFuncSetAttribute(edge_kernel, cudaFuncAttributeMaxDynamicSharedMemorySize, ESM);

    const int MB = (NN + 127) / 128;  // 782

    // 1) h1 = lrelu(atom @ W1^T + b1)
    tc_gemm<1><<<dim3(1, MB), 256, GSM>>>(atom, W1, b1, h1, NN, 128);
    // 2) nt = h1 @ Wa^T + ba
    tc_gemm<0><<<dim3(1, MB), 256, GSM>>>(h1, Wa, ba, nt, NN, 128);
    // 3) gh = h1 @ W_hh^T + b_hh
    tc_gemm<0><<<dim3(3, MB), 256, GSM>>>(h1, W_hh, b_hh, gh, NN, 384);
    // 4) fused edge kernel -> context
    edge_kernel<<<NN / 16, 256, ESM>>>(atom, bond, src, h1, W2, b2, Ww, bw, nt, ctx);
    // 5) gi = ctx @ W_ih^T + b_ih
    tc_gemm<0><<<dim3(3, MB), 256, GSM>>>(ctx, W_ih, b_ih, gi, NN, 384);
    // 6) combine -> final
    gru_combine<<<(NN * 32 + 255) / 256, 256>>>(gi, gh, h1, out);
}